// round 16
// baseline (speedup 1.0000x reference)
#include <cuda_runtime.h>
#include <math.h>

// ---------------------------------------------------------------------------
// HGP-SL GNN forward.  R16 = R15 + (a) build_k full-row load batching
// (MLP 4 -> 16 on the 134MB adj read), (b) mlp_fused readout loops
// unrolled x4 (MLP 1 -> 4).  All else identical to R15 (526us).
// ---------------------------------------------------------------------------

#define G   128
#define N1  512
#define FD  128
#define K1  256
#define K2  128
#define NCLS 10
#define MAXDEG 128

// ------------------------------- scratch -----------------------------------
__device__ __align__(16) float d_dinv [G * N1];
__device__ __align__(16) int   d_nnz  [G * N1];
__device__ __align__(16) int   d_cols [G * N1 * MAXDEG];
__device__ __align__(16) unsigned d_bits[G * N1 * (N1 / 32)];
__device__ __align__(16) float d_xw   [G * N1 * FD];
__device__ __align__(16) float d_scr  [G * N1 * FD];
__device__ __align__(16) float d_h1   [G * N1 * FD];
__device__ __align__(16) float d_score[G * N1];
__device__ __align__(16) int   d_idx1 [G * K1];
__device__ __align__(16) int   d_idx2 [G * K2];
__device__ __align__(16) float d_xk1  [G * K1 * FD];
__device__ __align__(16) float d_h2   [G * K1 * FD];
__device__ __align__(16) float d_xk2  [G * K2 * FD];
__device__ __align__(16) float d_h3   [G * K2 * FD];
__device__ __align__(16) float d_attn1[G * K1 * K1];
__device__ __align__(16) float d_attn2[G * K2 * K2];
__device__ __align__(16) float d_xs   [G * K1];
__device__ __align__(16) float d_xd   [G * K1];

// ----------------------- adjacency list + bitmap build -----------------------
// Entire 512-float row loaded (16 LDGs in flight) before the ballot chain.
__global__ void build_k(const float* __restrict__ adj, int* __restrict__ cols,
                        int* __restrict__ nnz, float* __restrict__ dinv,
                        unsigned* __restrict__ bits)
{
    int gw   = (blockIdx.x * blockDim.x + threadIdx.x) >> 5;
    int lane = threadIdx.x & 31;
    if (gw >= G * N1) return;
    const float* row = adj + (size_t)gw * N1;
    int* cl = cols + (size_t)gw * MAXDEG;
    unsigned* bw = bits + (size_t)gw * (N1 / 32);
    float vv[16];
#pragma unroll
    for (int q = 0; q < 16; q++) vv[q] = row[q * 32 + lane];
    int count = 0;
#pragma unroll
    for (int q = 0; q < 16; q++) {
        unsigned m = __ballot_sync(0xffffffffu, vv[q] != 0.f);
        if (lane == 0) bw[q] = m;
        if (vv[q] != 0.f) {
            int pos = count + __popc(m & ((1u << lane) - 1u));
            if (pos < MAXDEG) cl[pos] = q * 32 + lane;
        }
        count += __popc(m);
    }
    if (lane == 0) {
        nnz[gw]  = count;
        dinv[gw] = rsqrtf((float)count + 1.f);
    }
}

// --------------------- sparse GCN layer-1 aggregation ------------------------
__global__ void spmm_gcn1_k(const float* __restrict__ y, const float* __restrict__ xw,
                            const int* __restrict__ cols, const int* __restrict__ nnz,
                            const float* __restrict__ dinv, const float* __restrict__ b,
                            float* __restrict__ h1)
{
    int gw   = (blockIdx.x * blockDim.x + threadIdx.x) >> 5;
    int lane = threadIdx.x & 31;
    if (gw >= G * N1) return;
    int g = gw >> 9;
    const int4* cl4 = (const int4*)(cols + (size_t)gw * MAXDEG);
    const int*  cl  = cols + (size_t)gw * MAXDEG;
    int n = nnz[gw]; if (n > MAXDEG) n = MAXDEG;
    const float4* yg = (const float4*)(y + (size_t)g * N1 * FD);
    float4 acc = make_float4(0.f, 0.f, 0.f, 0.f);
    int t = 0;
    for (; t + 4 <= n; t += 4) {
        int4 c = cl4[t >> 2];
        float4 v0 = yg[c.x * 32 + lane];
        float4 v1 = yg[c.y * 32 + lane];
        float4 v2 = yg[c.z * 32 + lane];
        float4 v3 = yg[c.w * 32 + lane];
        acc.x += (v0.x + v1.x) + (v2.x + v3.x);
        acc.y += (v0.y + v1.y) + (v2.y + v3.y);
        acc.z += (v0.z + v1.z) + (v2.z + v3.z);
        acc.w += (v0.w + v1.w) + (v2.w + v3.w);
    }
    for (; t < n; t++) {
        float4 v = yg[cl[t] * 32 + lane];
        acc.x += v.x; acc.y += v.y; acc.z += v.z; acc.w += v.w;
    }
    float dv = dinv[gw], dv2 = dv * dv;
    float4 xv = ((const float4*)(xw + (size_t)gw * FD))[lane];
    float4 bv = ((const float4*)b)[lane];
    float4 o;
    o.x = fmaxf(dv * acc.x + dv2 * xv.x + bv.x, 0.f);
    o.y = fmaxf(dv * acc.y + dv2 * xv.y + bv.y, 0.f);
    o.z = fmaxf(dv * acc.z + dv2 * xv.z + bv.z, 0.f);
    o.w = fmaxf(dv * acc.w + dv2 * xv.w + bv.w, 0.f);
    ((float4*)(h1 + (size_t)gw * FD))[lane] = o;
}

// --------------------- sparse fused info-score -------------------------------
__global__ void spmm_score_k(const float* __restrict__ h, const int* __restrict__ cols,
                             const int* __restrict__ nnz, float* __restrict__ sc)
{
    int gw   = (blockIdx.x * blockDim.x + threadIdx.x) >> 5;
    int lane = threadIdx.x & 31;
    if (gw >= G * N1) return;
    int g = gw >> 9;
    const int4* cl4 = (const int4*)(cols + (size_t)gw * MAXDEG);
    const int*  cl  = cols + (size_t)gw * MAXDEG;
    int n = nnz[gw];
    float inv = 1.f / fmaxf((float)n, 1.f);
    if (n > MAXDEG) n = MAXDEG;
    const float4* hg = (const float4*)(h + (size_t)g * N1 * FD);
    float4 acc = make_float4(0.f, 0.f, 0.f, 0.f);
    int t = 0;
    for (; t + 4 <= n; t += 4) {
        int4 c = cl4[t >> 2];
        float4 v0 = hg[c.x * 32 + lane];
        float4 v1 = hg[c.y * 32 + lane];
        float4 v2 = hg[c.z * 32 + lane];
        float4 v3 = hg[c.w * 32 + lane];
        acc.x += (v0.x + v1.x) + (v2.x + v3.x);
        acc.y += (v0.y + v1.y) + (v2.y + v3.y);
        acc.z += (v0.z + v1.z) + (v2.z + v3.z);
        acc.w += (v0.w + v1.w) + (v2.w + v3.w);
    }
    for (; t < n; t++) {
        float4 v = hg[cl[t] * 32 + lane];
        acc.x += v.x; acc.y += v.y; acc.z += v.z; acc.w += v.w;
    }
    float4 hv = ((const float4*)(h + (size_t)gw * FD))[lane];
    float s = fabsf(hv.x - acc.x * inv) + fabsf(hv.y - acc.y * inv)
            + fabsf(hv.z - acc.z * inv) + fabsf(hv.w - acc.w * inv);
#pragma unroll
    for (int o = 16; o; o >>= 1) s += __shfl_xor_sync(0xffffffffu, s, o);
    if (lane == 0) sc[gw] = s;
}

// ------------------------------ dense GEMM ----------------------------------
// MODE 0: C = acc;  MODE 1: C = acc, out2 = dinv*acc;
// MODE 3: C = relu(0.5*(acc+aux)+bias);  MODE 4: out2[row] = sum|aux-acc|
#define BM2  128
#define BN2  128
#define BK2  16
#define BMP  132

template <int MODE>
__global__ __launch_bounds__(256, 2)
void gemm_k(const float* __restrict__ A, int aStride, int lda,
            const float* __restrict__ B, int bStride,
            float* __restrict__ C, int cStride,
            int Kdim,
            const float* __restrict__ aux, int auxStride,
            const float* __restrict__ dinv, int dinvStride,
            const float* __restrict__ bias,
            float* __restrict__ out2)
{
    __shared__ __align__(16) float As[2][BK2][BMP];
    __shared__ __align__(16) float Bs[2][BK2][BN2];
    int g  = blockIdx.y;
    int m0 = blockIdx.x * BM2;
    const float* Ag = A + (size_t)g * aStride;
    const float* Bg = B + (size_t)g * bStride;
    int t  = threadIdx.x;
    int tx = t & 15, ty = t >> 4;

    int aRow0 = (t) >> 2,        aQ0 = ((t) & 3) << 2;
    int aRow1 = (t + 256) >> 2,  aQ1 = ((t + 256) & 3) << 2;
    int bRow0 = (t) >> 5,        bQ0 = ((t) & 31) << 2;
    int bRow1 = (t + 256) >> 5,  bQ1 = ((t + 256) & 31) << 2;

    unsigned long long acc2[8][4];
#pragma unroll
    for (int r = 0; r < 8; r++)
#pragma unroll
        for (int c = 0; c < 4; c++) acc2[r][c] = 0ull;

    float4 pa0, pa1, pb0, pb1;
    pa0 = *(const float4*)(Ag + (size_t)(m0 + aRow0) * lda + aQ0);
    pa1 = *(const float4*)(Ag + (size_t)(m0 + aRow1) * lda + aQ1);
    pb0 = *(const float4*)(Bg + (size_t)bRow0 * BN2 + bQ0);
    pb1 = *(const float4*)(Bg + (size_t)bRow1 * BN2 + bQ1);
    As[0][aQ0 + 0][aRow0] = pa0.x; As[0][aQ0 + 1][aRow0] = pa0.y;
    As[0][aQ0 + 2][aRow0] = pa0.z; As[0][aQ0 + 3][aRow0] = pa0.w;
    As[0][aQ1 + 0][aRow1] = pa1.x; As[0][aQ1 + 1][aRow1] = pa1.y;
    As[0][aQ1 + 2][aRow1] = pa1.z; As[0][aQ1 + 3][aRow1] = pa1.w;
    *(float4*)&Bs[0][bRow0][bQ0] = pb0;
    *(float4*)&Bs[0][bRow1][bQ1] = pb1;
    __syncthreads();

    int buf = 0;
    for (int k0 = 0;;) {
        int kn = k0 + BK2;
        bool more = kn < Kdim;
        if (more) {
            pa0 = *(const float4*)(Ag + (size_t)(m0 + aRow0) * lda + kn + aQ0);
            pa1 = *(const float4*)(Ag + (size_t)(m0 + aRow1) * lda + kn + aQ1);
            pb0 = *(const float4*)(Bg + (size_t)(kn + bRow0) * BN2 + bQ0);
            pb1 = *(const float4*)(Bg + (size_t)(kn + bRow1) * BN2 + bQ1);
        }
#pragma unroll
        for (int k = 0; k < BK2; k++) {
            float4 a0 = *(const float4*)&As[buf][k][ty * 8];
            float4 a1 = *(const float4*)&As[buf][k][ty * 8 + 4];
            ulonglong2 bp0 = *(const ulonglong2*)&Bs[buf][k][tx * 8];
            ulonglong2 bp1 = *(const ulonglong2*)&Bs[buf][k][tx * 8 + 4];
            unsigned long long bv2[4] = {bp0.x, bp0.y, bp1.x, bp1.y};
            float av[8] = {a0.x, a0.y, a0.z, a0.w, a1.x, a1.y, a1.z, a1.w};
#pragma unroll
            for (int r = 0; r < 8; r++) {
                unsigned long long a2;
                unsigned au = __float_as_uint(av[r]);
                asm("mov.b64 %0, {%1, %1};" : "=l"(a2) : "r"(au));
#pragma unroll
                for (int c = 0; c < 4; c++)
                    asm("fma.rn.f32x2 %0, %1, %2, %0;"
                        : "+l"(acc2[r][c]) : "l"(a2), "l"(bv2[c]));
            }
        }
        if (!more) break;
        int nb = buf ^ 1;
        As[nb][aQ0 + 0][aRow0] = pa0.x; As[nb][aQ0 + 1][aRow0] = pa0.y;
        As[nb][aQ0 + 2][aRow0] = pa0.z; As[nb][aQ0 + 3][aRow0] = pa0.w;
        As[nb][aQ1 + 0][aRow1] = pa1.x; As[nb][aQ1 + 1][aRow1] = pa1.y;
        As[nb][aQ1 + 2][aRow1] = pa1.z; As[nb][aQ1 + 3][aRow1] = pa1.w;
        *(float4*)&Bs[nb][bRow0][bQ0] = pb0;
        *(float4*)&Bs[nb][bRow1][bQ1] = pb1;
        __syncthreads();
        buf = nb;
        k0 = kn;
    }

    float acc[8][8];
#pragma unroll
    for (int r = 0; r < 8; r++)
#pragma unroll
        for (int c = 0; c < 4; c++) {
            unsigned lo, hi;
            asm("mov.b64 {%0, %1}, %2;" : "=r"(lo), "=r"(hi) : "l"(acc2[r][c]));
            acc[r][2 * c]     = __uint_as_float(lo);
            acc[r][2 * c + 1] = __uint_as_float(hi);
        }

    if (MODE == 4) {
#pragma unroll
        for (int r = 0; r < 8; r++) {
            int row = m0 + ty * 8 + r;
            const float* ax = aux + (size_t)g * auxStride + (size_t)row * BN2 + tx * 8;
            float local = 0.f;
#pragma unroll
            for (int c = 0; c < 8; c++) local += fabsf(ax[c] - acc[r][c]);
#pragma unroll
            for (int o = 8; o; o >>= 1) local += __shfl_xor_sync(0xffffffffu, local, o);
            if (tx == 0) out2[g * cStride + row] = local;
        }
    } else {
#pragma unroll
        for (int r = 0; r < 8; r++) {
            int row = m0 + ty * 8 + r;
            size_t base = (size_t)g * cStride + (size_t)row * BN2 + tx * 8;
            if (MODE == 0) {
                *(float4*)(C + base)     = make_float4(acc[r][0], acc[r][1], acc[r][2], acc[r][3]);
                *(float4*)(C + base + 4) = make_float4(acc[r][4], acc[r][5], acc[r][6], acc[r][7]);
            } else if (MODE == 1) {
                float dv = dinv[g * dinvStride + row];
                float4 v0 = make_float4(acc[r][0], acc[r][1], acc[r][2], acc[r][3]);
                float4 v1 = make_float4(acc[r][4], acc[r][5], acc[r][6], acc[r][7]);
                *(float4*)(C + base)     = v0;
                *(float4*)(C + base + 4) = v1;
                *(float4*)(out2 + base)     = make_float4(dv * v0.x, dv * v0.y, dv * v0.z, dv * v0.w);
                *(float4*)(out2 + base + 4) = make_float4(dv * v1.x, dv * v1.y, dv * v1.z, dv * v1.w);
            } else {  // MODE 3
                const float* ax = aux + (size_t)g * auxStride + (size_t)row * BN2 + tx * 8;
                float4 x0 = *(const float4*)ax;
                float4 x1 = *(const float4*)(ax + 4);
                const float4 bb0 = *(const float4*)(bias + tx * 8);
                const float4 bb1 = *(const float4*)(bias + tx * 8 + 4);
                float4 v0, v1;
                v0.x = fmaxf(0.5f * (acc[r][0] + x0.x) + bb0.x, 0.f);
                v0.y = fmaxf(0.5f * (acc[r][1] + x0.y) + bb0.y, 0.f);
                v0.z = fmaxf(0.5f * (acc[r][2] + x0.z) + bb0.z, 0.f);
                v0.w = fmaxf(0.5f * (acc[r][3] + x0.w) + bb0.w, 0.f);
                v1.x = fmaxf(0.5f * (acc[r][4] + x1.x) + bb1.x, 0.f);
                v1.y = fmaxf(0.5f * (acc[r][5] + x1.y) + bb1.y, 0.f);
                v1.z = fmaxf(0.5f * (acc[r][6] + x1.z) + bb1.z, 0.f);
                v1.w = fmaxf(0.5f * (acc[r][7] + x1.w) + bb1.w, 0.f);
                *(float4*)(C + base)     = v0;
                *(float4*)(C + base + 4) = v1;
            }
        }
    }
}

// ---------------- fused top-k + gather + attention dots ----------------------
template <int NTH, int KSEL>
__global__ void topk_gather_k(const float* __restrict__ sc,
                              const float* __restrict__ h, int Nsrc,
                              const float* __restrict__ atts,
                              const float* __restrict__ attd,
                              int* __restrict__ outIdx, float* __restrict__ xk,
                              float* __restrict__ xs, float* __restrict__ xd)
{
    __shared__ unsigned long long keys[NTH];
    __shared__ int sidx[KSEL];
    int g = blockIdx.x, t = threadIdx.x;
    float v = sc[g * NTH + t];
    unsigned u = __float_as_uint(v);
    u = (u & 0x80000000u) ? ~u : (u | 0x80000000u);
    keys[t] = (((unsigned long long)(~u)) << 32) | (unsigned)t;
    __syncthreads();
    for (int kk = 2; kk <= NTH; kk <<= 1) {
        for (int j = kk >> 1; j > 0; j >>= 1) {
            int ixj = t ^ j;
            if (ixj > t) {
                unsigned long long a = keys[t], b = keys[ixj];
                bool dir = ((t & kk) == 0);
                if ((a > b) == dir) { keys[t] = b; keys[ixj] = a; }
            }
            __syncthreads();
        }
    }
    if (t < KSEL) {
        int id = (int)(keys[t] & 0xffffffffu);
        sidx[t] = id;
        outIdx[g * KSEL + t] = id;
    }
    __syncthreads();

    int warp = t >> 5, lane = t & 31;
    const int nw = NTH / 32;
    float4 as4 = ((const float4*)atts)[lane];
    float4 ad4 = ((const float4*)attd)[lane];
    for (int i = warp; i < KSEL; i += nw) {
        int src = sidx[i];
        float4 vv = ((const float4*)(h + ((size_t)g * Nsrc + src) * FD))[lane];
        ((float4*)(xk + ((size_t)g * KSEL + i) * FD))[lane] = vv;
        float ps = vv.x * as4.x + vv.y * as4.y + vv.z * as4.z + vv.w * as4.w;
        float pd = vv.x * ad4.x + vv.y * ad4.y + vv.z * ad4.z + vv.w * ad4.w;
#pragma unroll
        for (int o = 16; o; o >>= 1) {
            ps += __shfl_xor_sync(0xffffffffu, ps, o);
            pd += __shfl_xor_sync(0xffffffffu, pd, o);
        }
        if (lane == 0) {
            xs[g * KSEL + i] = ps;
            xd[g * KSEL + i] = pd;
        }
    }
}

// -------- attention + softmax, phase A: warp-per-row, 8 rows/block -----------
__global__ __launch_bounds__(256)
void attn_bitmap8_k(const float* __restrict__ xs, const float* __restrict__ xd,
                    const int* __restrict__ idx, const unsigned* __restrict__ bits,
                    float* __restrict__ attn)
{
    __shared__ int   sidx[K1];
    __shared__ float sxd[K1];
    __shared__ unsigned sbw[8][N1 / 32];
    int g = blockIdx.y, t = threadIdx.x;
    int warp = t >> 5, lane = t & 31;
    int i = blockIdx.x * 8 + warp;

    sidx[t] = idx[g * K1 + t];
    sxd[t]  = xd[g * K1 + t];
    __syncthreads();

    int ii = sidx[i];
    if (lane < N1 / 32)
        sbw[warp][lane] = bits[((size_t)g * N1 + ii) * (N1 / 32) + lane];
    __syncwarp();

    float xsi = xs[g * K1 + i];
    int j0 = lane * 8;
    int4  i4a = ((const int4*)sidx)[lane * 2];
    int4  i4b = ((const int4*)sidx)[lane * 2 + 1];
    float4 xda = ((const float4*)sxd)[lane * 2];
    float4 xdb = ((const float4*)sxd)[lane * 2 + 1];
    int   jj[8] = {i4a.x, i4a.y, i4a.z, i4a.w, i4b.x, i4b.y, i4b.z, i4b.w};
    float xv[8] = {xda.x, xda.y, xda.z, xda.w, xdb.x, xdb.y, xdb.z, xdb.w};

    float e[8], mx = -3.402823466e+38f;
#pragma unroll
    for (int c = 0; c < 8; c++) {
        float v = xsi + xv[c];
        v = v > 0.f ? v : 0.2f * v;
        int q = jj[c];
        v += (float)((sbw[warp][q >> 5] >> (q & 31)) & 1u);
        e[c] = v;
        mx = fmaxf(mx, v);
    }
#pragma unroll
    for (int o = 16; o; o >>= 1) mx = fmaxf(mx, __shfl_xor_sync(0xffffffffu, mx, o));
    float p[8], s = 0.f;
#pragma unroll
    for (int c = 0; c < 8; c++) { p[c] = expf(e[c] - mx); s += p[c]; }
#pragma unroll
    for (int o = 16; o; o >>= 1) s += __shfl_xor_sync(0xffffffffu, s, o);
    float inv = 1.f / s;
    float* dst = attn + ((size_t)g * K1 + i) * K1 + j0;
    *(float4*)(dst)     = make_float4(p[0] * inv, p[1] * inv, p[2] * inv, p[3] * inv);
    *(float4*)(dst + 4) = make_float4(p[4] * inv, p[5] * inv, p[6] * inv, p[7] * inv);
}

// -------- attention + softmax, phase B: warp-per-row, 8 rows/block -----------
__global__ __launch_bounds__(256)
void attn_row8_k(const float* __restrict__ xs, const float* __restrict__ xd,
                 const int* __restrict__ idx, const float* __restrict__ adjsrc,
                 float* __restrict__ attn)
{
    __shared__ int   sidx[K2];
    __shared__ float sxd[K2];
    __shared__ float srow[8][K1];
    int g = blockIdx.y, t = threadIdx.x;
    int warp = t >> 5, lane = t & 31;
    int i = blockIdx.x * 8 + warp;

    if (t < K2) {
        sidx[t] = idx[g * K2 + t];
        sxd[t]  = xd[g * K2 + t];
    }
    __syncthreads();

    int ii = sidx[i];
    const float4* src4 = (const float4*)(adjsrc + ((size_t)g * K1 + ii) * K1);
    ((float4*)srow[warp])[lane]      = src4[lane];
    ((float4*)srow[warp])[lane + 32] = src4[lane + 32];
    __syncwarp();

    float xsi = xs[g * K2 + i];
    int j0 = lane * 4;
    int4   i4 = ((const int4*)sidx)[lane];
    float4 xv4 = ((const float4*)sxd)[lane];
    int   jj[4] = {i4.x, i4.y, i4.z, i4.w};
    float xv[4] = {xv4.x, xv4.y, xv4.z, xv4.w};

    float e[4], mx = -3.402823466e+38f;
#pragma unroll
    for (int c = 0; c < 4; c++) {
        float v = xsi + xv[c];
        v = v > 0.f ? v : 0.2f * v;
        v += srow[warp][jj[c]];
        e[c] = v;
        mx = fmaxf(mx, v);
    }
#pragma unroll
    for (int o = 16; o; o >>= 1) mx = fmaxf(mx, __shfl_xor_sync(0xffffffffu, mx, o));
    float p[4], s = 0.f;
#pragma unroll
    for (int c = 0; c < 4; c++) { p[c] = expf(e[c] - mx); s += p[c]; }
#pragma unroll
    for (int o = 16; o; o >>= 1) s += __shfl_xor_sync(0xffffffffu, s, o);
    float inv = 1.f / s;
    float* dst = attn + ((size_t)g * K2 + i) * K2 + j0;
    *(float4*)dst = make_float4(p[0] * inv, p[1] * inv, p[2] * inv, p[3] * inv);
}

// ------------------- fused readouts + MLP head (per graph) -------------------
__global__ void mlp_fused_k(const float* __restrict__ xk1,
                            const float* __restrict__ xk2,
                            const float* __restrict__ h3,
                            const float* __restrict__ Wl1, const float* __restrict__ bl1,
                            const float* __restrict__ Wl2, const float* __restrict__ bl2,
                            const float* __restrict__ Wl3, const float* __restrict__ bl3,
                            float* __restrict__ out)
{
    int g = blockIdx.x, t = threadIdx.x;   // 128 threads
    __shared__ float z[256], z1[128], z2[64], lg[NCLS];
    const float NEGINF = -3.402823466e+38f;

    float mx1 = NEGINF, sm1 = 0.f;
    {
        const float* p = xk1 + (size_t)g * K1 * FD + t;
#pragma unroll 1
        for (int i = 0; i < K1; i += 4) {
            float v0 = p[(size_t)(i + 0) * FD];
            float v1 = p[(size_t)(i + 1) * FD];
            float v2 = p[(size_t)(i + 2) * FD];
            float v3 = p[(size_t)(i + 3) * FD];
            mx1 = fmaxf(mx1, fmaxf(fmaxf(v0, v1), fmaxf(v2, v3)));
            sm1 += (v0 + v1) + (v2 + v3);
        }
    }
    float mx2 = NEGINF, sm2 = 0.f;
    {
        const float* p = xk2 + (size_t)g * K2 * FD + t;
#pragma unroll 1
        for (int i = 0; i < K2; i += 4) {
            float v0 = p[(size_t)(i + 0) * FD];
            float v1 = p[(size_t)(i + 1) * FD];
            float v2 = p[(size_t)(i + 2) * FD];
            float v3 = p[(size_t)(i + 3) * FD];
            mx2 = fmaxf(mx2, fmaxf(fmaxf(v0, v1), fmaxf(v2, v3)));
            sm2 += (v0 + v1) + (v2 + v3);
        }
    }
    float mx3 = NEGINF, sm3 = 0.f;
    {
        const float* p = h3 + (size_t)g * K2 * FD + t;
#pragma unroll 1
        for (int i = 0; i < K2; i += 4) {
            float v0 = p[(size_t)(i + 0) * FD];
            float v1 = p[(size_t)(i + 1) * FD];
            float v2 = p[(size_t)(i + 2) * FD];
            float v3 = p[(size_t)(i + 3) * FD];
            mx3 = fmaxf(mx3, fmaxf(fmaxf(v0, v1), fmaxf(v2, v3)));
            sm3 += (v0 + v1) + (v2 + v3);
        }
    }
    z[t]       = fmaxf(mx1, 0.f) + fmaxf(mx2, 0.f) + fmaxf(mx3, 0.f);
    z[128 + t] = fmaxf(sm1 / (float)K1, 0.f) + fmaxf(sm2 / (float)K2, 0.f)
               + fmaxf(sm3 / (float)K2, 0.f);
    __syncthreads();

    float a = bl1[t];
    for (int j = 0; j < 256; j++) a += z[j] * Wl1[j * 128 + t];
    z1[t] = fmaxf(a, 0.f);
    __syncthreads();
    if (t < 64) {
        float b = bl2[t];
        for (int j = 0; j < 128; j++) b += z1[j] * Wl2[j * 64 + t];
        z2[t] = fmaxf(b, 0.f);
    }
    __syncthreads();
    if (t < NCLS) {
        float c = bl3[t];
        for (int j = 0; j < 64; j++) c += z2[j] * Wl3[j * NCLS + t];
        lg[t] = c;
    }
    __syncthreads();
    if (t < NCLS) {
        float m = lg[0];
        for (int cc = 1; cc < NCLS; cc++) m = fmaxf(m, lg[cc]);
        float s = 0.f;
        for (int cc = 0; cc < NCLS; cc++) s += expf(lg[cc] - m);
        out[g * NCLS + t] = expf(lg[t] - m) / s;
    }
}

// ------------------------------ orchestration --------------------------------
extern "C" void kernel_launch(void* const* d_in, const int* in_sizes, int n_in,
                              void* d_out, int out_size)
{
    const float* x   = (const float*)d_in[0];
    const float* adj = (const float*)d_in[1];
    const float* W1  = (const float*)d_in[2];
    const float* b1  = (const float*)d_in[3];
    const float* W2  = (const float*)d_in[4];
    const float* b2  = (const float*)d_in[5];
    const float* W3  = (const float*)d_in[6];
    const float* b3  = (const float*)d_in[7];
    const float* a1s = (const float*)d_in[8];
    const float* a1d = (const float*)d_in[9];
    const float* a2s = (const float*)d_in[10];
    const float* a2d = (const float*)d_in[11];
    const float* Wl1 = (const float*)d_in[12];
    const float* bl1 = (const float*)d_in[13];
    const float* Wl2 = (const float*)d_in[14];
    const float* bl2 = (const float*)d_in[15];
    const float* Wl3 = (const float*)d_in[16];
    const float* bl3 = (const float*)d_in[17];
    float* out = (float*)d_out;

    float *p_dinv, *p_xw, *p_scr, *p_h1, *p_score, *p_xk1, *p_h2,
          *p_xk2, *p_h3, *p_attn1, *p_attn2, *p_xs, *p_xd;
    int *p_idx1, *p_idx2, *p_nnz, *p_cols;
    unsigned* p_bits;
    cudaGetSymbolAddress((void**)&p_dinv,  d_dinv);
    cudaGetSymbolAddress((void**)&p_nnz,   d_nnz);
    cudaGetSymbolAddress((void**)&p_cols,  d_cols);
    cudaGetSymbolAddress((void**)&p_bits,  d_bits);
    cudaGetSymbolAddress((void**)&p_xw,    d_xw);
    cudaGetSymbolAddress((void**)&p_scr,   d_scr);
    cudaGetSymbolAddress((void**)&p_h1,    d_h1);
    cudaGetSymbolAddress((void**)&p_score, d_score);
    cudaGetSymbolAddress((void**)&p_idx1,  d_idx1);
    cudaGetSymbolAddress((void**)&p_idx2,  d_idx2);
    cudaGetSymbolAddress((void**)&p_xk1,   d_xk1);
    cudaGetSymbolAddress((void**)&p_h2,    d_h2);
    cudaGetSymbolAddress((void**)&p_xk2,   d_xk2);
    cudaGetSymbolAddress((void**)&p_h3,    d_h3);
    cudaGetSymbolAddress((void**)&p_attn1, d_attn1);
    cudaGetSymbolAddress((void**)&p_attn2, d_attn2);
    cudaGetSymbolAddress((void**)&p_xs,    d_xs);
    cudaGetSymbolAddress((void**)&p_xd,    d_xd);

    // ---- Phase A (N = 512) ----
    build_k<<<(G * N1) / 8, 256>>>(adj, p_cols, p_nnz, p_dinv, p_bits);
    gemm_k<1><<<dim3(N1 / BM2, G), 256>>>(x, N1 * FD, FD, W1, 0,
                                          p_xw, N1 * FD, FD,
                                          nullptr, 0, p_dinv, N1, nullptr, p_scr);
    spmm_gcn1_k<<<(G * N1) / 8, 256>>>(p_scr, p_xw, p_cols, p_nnz, p_dinv, b1, p_h1);
    spmm_score_k<<<(G * N1) / 8, 256>>>(p_h1, p_cols, p_nnz, p_score);
    topk_gather_k<N1, K1><<<G, N1>>>(p_score, p_h1, N1, a1s, a1d,
                                     p_idx1, p_xk1, p_xs, p_xd);
    attn_bitmap8_k<<<dim3(K1 / 8, G), 256>>>(p_xs, p_xd, p_idx1, p_bits, p_attn1);

    // ---- Phase B (N = 256) ----
    gemm_k<0><<<dim3(K1 / BM2, G), 256>>>(p_xk1, K1 * FD, FD, W2, 0,
                                          p_xw, K1 * FD, FD,
                                          nullptr, 0, nullptr, 0, nullptr, nullptr);
    gemm_k<3><<<dim3(K1 / BM2, G), 256>>>(p_attn1, K1 * K1, K1, p_xw, K1 * FD,
                                          p_h2, K1 * FD, K1,
                                          p_xw, K1 * FD, nullptr, 0, b2, nullptr);
    gemm_k<4><<<dim3(K1 / BM2, G), 256>>>(p_attn1, K1 * K1, K1, p_h2, K1 * FD,
                                          nullptr, K1, K1,
                                          p_h2, K1 * FD, nullptr, 0, nullptr, p_score);
    topk_gather_k<K1, K2><<<G, K1>>>(p_score, p_h2, K1, a2s, a2d,
                                     p_idx2, p_xk2, p_xs, p_xd);
    attn_row8_k<<<dim3(K2 / 8, G), 256>>>(p_xs, p_xd, p_idx2, p_attn1, p_attn2);

    // ---- Phase C (N = 128) ----
    gemm_k<0><<<dim3(K2 / BM2, G), 256>>>(p_xk2, K2 * FD, FD, W3, 0,
                                          p_xw, K2 * FD, FD,
                                          nullptr, 0, nullptr, 0, nullptr, nullptr);
    gemm_k<3><<<dim3(K2 / BM2, G), 256>>>(p_attn2, K2 * K2, K2, p_xw, K2 * FD,
                                          p_h3, K2 * FD, K2,
                                          p_xw, K2 * FD, nullptr, 0, b3, nullptr);

    // ---- Readouts + head (fused) ----
    mlp_fused_k<<<G, 128>>>(p_xk1, p_xk2, p_h3,
                            Wl1, bl1, Wl2, bl2, Wl3, bl3, out);
}

// round 17
// speedup vs baseline: 1.0781x; 1.0781x over previous
#include <cuda_runtime.h>
#include <math.h>

// ---------------------------------------------------------------------------
// HGP-SL GNN forward.  R17 = exact R15 (best: 526us) + single change:
// phase-A GEMM writes only y = dinv*xw (mode 2); xw store (33.5MB)
// eliminated; spmm_gcn1 self-term dv^2*xw == dv*y_self computed from y.
// R16's 16-deep build batching reverted (cross-CTA L1tex queue regression).
// ---------------------------------------------------------------------------

#define G   128
#define N1  512
#define FD  128
#define K1  256
#define K2  128
#define NCLS 10
#define MAXDEG 128

// ------------------------------- scratch -----------------------------------
__device__ __align__(16) float d_dinv [G * N1];
__device__ __align__(16) int   d_nnz  [G * N1];
__device__ __align__(16) int   d_cols [G * N1 * MAXDEG];
__device__ __align__(16) unsigned d_bits[G * N1 * (N1 / 32)];
__device__ __align__(16) float d_xw   [G * N1 * FD];
__device__ __align__(16) float d_scr  [G * N1 * FD];
__device__ __align__(16) float d_h1   [G * N1 * FD];
__device__ __align__(16) float d_score[G * N1];
__device__ __align__(16) int   d_idx1 [G * K1];
__device__ __align__(16) int   d_idx2 [G * K2];
__device__ __align__(16) float d_xk1  [G * K1 * FD];
__device__ __align__(16) float d_h2   [G * K1 * FD];
__device__ __align__(16) float d_xk2  [G * K2 * FD];
__device__ __align__(16) float d_h3   [G * K2 * FD];
__device__ __align__(16) float d_attn1[G * K1 * K1];
__device__ __align__(16) float d_attn2[G * K2 * K2];
__device__ __align__(16) float d_xs   [G * K1];
__device__ __align__(16) float d_xd   [G * K1];

// ----------------------- adjacency list + bitmap build -----------------------
__global__ void build_k(const float* __restrict__ adj, int* __restrict__ cols,
                        int* __restrict__ nnz, float* __restrict__ dinv,
                        unsigned* __restrict__ bits)
{
    int gw   = (blockIdx.x * blockDim.x + threadIdx.x) >> 5;
    int lane = threadIdx.x & 31;
    if (gw >= G * N1) return;
    const float* row = adj + (size_t)gw * N1;
    int* cl = cols + (size_t)gw * MAXDEG;
    unsigned* bw = bits + (size_t)gw * (N1 / 32);
    int count = 0;
#pragma unroll
    for (int j0 = 0; j0 < N1; j0 += 128) {
        float v0 = row[j0 + lane];
        float v1 = row[j0 + 32 + lane];
        float v2 = row[j0 + 64 + lane];
        float v3 = row[j0 + 96 + lane];
        float vv[4] = {v0, v1, v2, v3};
#pragma unroll
        for (int q = 0; q < 4; q++) {
            unsigned m = __ballot_sync(0xffffffffu, vv[q] != 0.f);
            if (lane == 0) bw[(j0 >> 5) + q] = m;
            if (vv[q] != 0.f) {
                int pos = count + __popc(m & ((1u << lane) - 1u));
                if (pos < MAXDEG) cl[pos] = j0 + q * 32 + lane;
            }
            count += __popc(m);
        }
    }
    if (lane == 0) {
        nnz[gw]  = count;
        dinv[gw] = rsqrtf((float)count + 1.f);
    }
}

// --------------------- sparse GCN layer-1 aggregation ------------------------
// y = dinv*xw.  h1 = relu(dv*(sum_nbr y + y_self) + b)   [dv^2*xw == dv*y_self]
__global__ void spmm_gcn1_k(const float* __restrict__ y,
                            const int* __restrict__ cols, const int* __restrict__ nnz,
                            const float* __restrict__ dinv, const float* __restrict__ b,
                            float* __restrict__ h1)
{
    int gw   = (blockIdx.x * blockDim.x + threadIdx.x) >> 5;
    int lane = threadIdx.x & 31;
    if (gw >= G * N1) return;
    int g = gw >> 9;
    const int4* cl4 = (const int4*)(cols + (size_t)gw * MAXDEG);
    const int*  cl  = cols + (size_t)gw * MAXDEG;
    int n = nnz[gw]; if (n > MAXDEG) n = MAXDEG;
    const float4* yg = (const float4*)(y + (size_t)g * N1 * FD);
    float4 acc = make_float4(0.f, 0.f, 0.f, 0.f);
    int t = 0;
    for (; t + 4 <= n; t += 4) {
        int4 c = cl4[t >> 2];
        float4 v0 = yg[c.x * 32 + lane];
        float4 v1 = yg[c.y * 32 + lane];
        float4 v2 = yg[c.z * 32 + lane];
        float4 v3 = yg[c.w * 32 + lane];
        acc.x += (v0.x + v1.x) + (v2.x + v3.x);
        acc.y += (v0.y + v1.y) + (v2.y + v3.y);
        acc.z += (v0.z + v1.z) + (v2.z + v3.z);
        acc.w += (v0.w + v1.w) + (v2.w + v3.w);
    }
    for (; t < n; t++) {
        float4 v = yg[cl[t] * 32 + lane];
        acc.x += v.x; acc.y += v.y; acc.z += v.z; acc.w += v.w;
    }
    float dv = dinv[gw];
    float4 ys = ((const float4*)(y + (size_t)gw * FD))[lane];
    float4 bv = ((const float4*)b)[lane];
    float4 o;
    o.x = fmaxf(dv * (acc.x + ys.x) + bv.x, 0.f);
    o.y = fmaxf(dv * (acc.y + ys.y) + bv.y, 0.f);
    o.z = fmaxf(dv * (acc.z + ys.z) + bv.z, 0.f);
    o.w = fmaxf(dv * (acc.w + ys.w) + bv.w, 0.f);
    ((float4*)(h1 + (size_t)gw * FD))[lane] = o;
}

// --------------------- sparse fused info-score -------------------------------
__global__ void spmm_score_k(const float* __restrict__ h, const int* __restrict__ cols,
                             const int* __restrict__ nnz, float* __restrict__ sc)
{
    int gw   = (blockIdx.x * blockDim.x + threadIdx.x) >> 5;
    int lane = threadIdx.x & 31;
    if (gw >= G * N1) return;
    int g = gw >> 9;
    const int4* cl4 = (const int4*)(cols + (size_t)gw * MAXDEG);
    const int*  cl  = cols + (size_t)gw * MAXDEG;
    int n = nnz[gw];
    float inv = 1.f / fmaxf((float)n, 1.f);
    if (n > MAXDEG) n = MAXDEG;
    const float4* hg = (const float4*)(h + (size_t)g * N1 * FD);
    float4 acc = make_float4(0.f, 0.f, 0.f, 0.f);
    int t = 0;
    for (; t + 4 <= n; t += 4) {
        int4 c = cl4[t >> 2];
        float4 v0 = hg[c.x * 32 + lane];
        float4 v1 = hg[c.y * 32 + lane];
        float4 v2 = hg[c.z * 32 + lane];
        float4 v3 = hg[c.w * 32 + lane];
        acc.x += (v0.x + v1.x) + (v2.x + v3.x);
        acc.y += (v0.y + v1.y) + (v2.y + v3.y);
        acc.z += (v0.z + v1.z) + (v2.z + v3.z);
        acc.w += (v0.w + v1.w) + (v2.w + v3.w);
    }
    for (; t < n; t++) {
        float4 v = hg[cl[t] * 32 + lane];
        acc.x += v.x; acc.y += v.y; acc.z += v.z; acc.w += v.w;
    }
    float4 hv = ((const float4*)(h + (size_t)gw * FD))[lane];
    float s = fabsf(hv.x - acc.x * inv) + fabsf(hv.y - acc.y * inv)
            + fabsf(hv.z - acc.z * inv) + fabsf(hv.w - acc.w * inv);
#pragma unroll
    for (int o = 16; o; o >>= 1) s += __shfl_xor_sync(0xffffffffu, s, o);
    if (lane == 0) sc[gw] = s;
}

// ------------------------------ dense GEMM ----------------------------------
// MODE 0: C = acc;  MODE 2: C = dinv[row] * acc (single output);
// MODE 3: C = relu(0.5*(acc+aux)+bias);  MODE 4: out2[row] = sum|aux-acc|
#define BM2  128
#define BN2  128
#define BK2  16
#define BMP  132

template <int MODE>
__global__ __launch_bounds__(256, 2)
void gemm_k(const float* __restrict__ A, int aStride, int lda,
            const float* __restrict__ B, int bStride,
            float* __restrict__ C, int cStride,
            int Kdim,
            const float* __restrict__ aux, int auxStride,
            const float* __restrict__ dinv, int dinvStride,
            const float* __restrict__ bias,
            float* __restrict__ out2)
{
    __shared__ __align__(16) float As[2][BK2][BMP];
    __shared__ __align__(16) float Bs[2][BK2][BN2];
    int g  = blockIdx.y;
    int m0 = blockIdx.x * BM2;
    const float* Ag = A + (size_t)g * aStride;
    const float* Bg = B + (size_t)g * bStride;
    int t  = threadIdx.x;
    int tx = t & 15, ty = t >> 4;

    int aRow0 = (t) >> 2,        aQ0 = ((t) & 3) << 2;
    int aRow1 = (t + 256) >> 2,  aQ1 = ((t + 256) & 3) << 2;
    int bRow0 = (t) >> 5,        bQ0 = ((t) & 31) << 2;
    int bRow1 = (t + 256) >> 5,  bQ1 = ((t + 256) & 31) << 2;

    unsigned long long acc2[8][4];
#pragma unroll
    for (int r = 0; r < 8; r++)
#pragma unroll
        for (int c = 0; c < 4; c++) acc2[r][c] = 0ull;

    float4 pa0, pa1, pb0, pb1;
    pa0 = *(const float4*)(Ag + (size_t)(m0 + aRow0) * lda + aQ0);
    pa1 = *(const float4*)(Ag + (size_t)(m0 + aRow1) * lda + aQ1);
    pb0 = *(const float4*)(Bg + (size_t)bRow0 * BN2 + bQ0);
    pb1 = *(const float4*)(Bg + (size_t)bRow1 * BN2 + bQ1);
    As[0][aQ0 + 0][aRow0] = pa0.x; As[0][aQ0 + 1][aRow0] = pa0.y;
    As[0][aQ0 + 2][aRow0] = pa0.z; As[0][aQ0 + 3][aRow0] = pa0.w;
    As[0][aQ1 + 0][aRow1] = pa1.x; As[0][aQ1 + 1][aRow1] = pa1.y;
    As[0][aQ1 + 2][aRow1] = pa1.z; As[0][aQ1 + 3][aRow1] = pa1.w;
    *(float4*)&Bs[0][bRow0][bQ0] = pb0;
    *(float4*)&Bs[0][bRow1][bQ1] = pb1;
    __syncthreads();

    int buf = 0;
    for (int k0 = 0;;) {
        int kn = k0 + BK2;
        bool more = kn < Kdim;
        if (more) {
            pa0 = *(const float4*)(Ag + (size_t)(m0 + aRow0) * lda + kn + aQ0);
            pa1 = *(const float4*)(Ag + (size_t)(m0 + aRow1) * lda + kn + aQ1);
            pb0 = *(const float4*)(Bg + (size_t)(kn + bRow0) * BN2 + bQ0);
            pb1 = *(const float4*)(Bg + (size_t)(kn + bRow1) * BN2 + bQ1);
        }
#pragma unroll
        for (int k = 0; k < BK2; k++) {
            float4 a0 = *(const float4*)&As[buf][k][ty * 8];
            float4 a1 = *(const float4*)&As[buf][k][ty * 8 + 4];
            ulonglong2 bp0 = *(const ulonglong2*)&Bs[buf][k][tx * 8];
            ulonglong2 bp1 = *(const ulonglong2*)&Bs[buf][k][tx * 8 + 4];
            unsigned long long bv2[4] = {bp0.x, bp0.y, bp1.x, bp1.y};
            float av[8] = {a0.x, a0.y, a0.z, a0.w, a1.x, a1.y, a1.z, a1.w};
#pragma unroll
            for (int r = 0; r < 8; r++) {
                unsigned long long a2;
                unsigned au = __float_as_uint(av[r]);
                asm("mov.b64 %0, {%1, %1};" : "=l"(a2) : "r"(au));
#pragma unroll
                for (int c = 0; c < 4; c++)
                    asm("fma.rn.f32x2 %0, %1, %2, %0;"
                        : "+l"(acc2[r][c]) : "l"(a2), "l"(bv2[c]));
            }
        }
        if (!more) break;
        int nb = buf ^ 1;
        As[nb][aQ0 + 0][aRow0] = pa0.x; As[nb][aQ0 + 1][aRow0] = pa0.y;
        As[nb][aQ0 + 2][aRow0] = pa0.z; As[nb][aQ0 + 3][aRow0] = pa0.w;
        As[nb][aQ1 + 0][aRow1] = pa1.x; As[nb][aQ1 + 1][aRow1] = pa1.y;
        As[nb][aQ1 + 2][aRow1] = pa1.z; As[nb][aQ1 + 3][aRow1] = pa1.w;
        *(float4*)&Bs[nb][bRow0][bQ0] = pb0;
        *(float4*)&Bs[nb][bRow1][bQ1] = pb1;
        __syncthreads();
        buf = nb;
        k0 = kn;
    }

    float acc[8][8];
#pragma unroll
    for (int r = 0; r < 8; r++)
#pragma unroll
        for (int c = 0; c < 4; c++) {
            unsigned lo, hi;
            asm("mov.b64 {%0, %1}, %2;" : "=r"(lo), "=r"(hi) : "l"(acc2[r][c]));
            acc[r][2 * c]     = __uint_as_float(lo);
            acc[r][2 * c + 1] = __uint_as_float(hi);
        }

    if (MODE == 4) {
#pragma unroll
        for (int r = 0; r < 8; r++) {
            int row = m0 + ty * 8 + r;
            const float* ax = aux + (size_t)g * auxStride + (size_t)row * BN2 + tx * 8;
            float local = 0.f;
#pragma unroll
            for (int c = 0; c < 8; c++) local += fabsf(ax[c] - acc[r][c]);
#pragma unroll
            for (int o = 8; o; o >>= 1) local += __shfl_xor_sync(0xffffffffu, local, o);
            if (tx == 0) out2[g * cStride + row] = local;
        }
    } else {
#pragma unroll
        for (int r = 0; r < 8; r++) {
            int row = m0 + ty * 8 + r;
            size_t base = (size_t)g * cStride + (size_t)row * BN2 + tx * 8;
            if (MODE == 0) {
                *(float4*)(C + base)     = make_float4(acc[r][0], acc[r][1], acc[r][2], acc[r][3]);
                *(float4*)(C + base + 4) = make_float4(acc[r][4], acc[r][5], acc[r][6], acc[r][7]);
            } else if (MODE == 2) {
                float dv = dinv[g * dinvStride + row];
                *(float4*)(C + base)     = make_float4(dv * acc[r][0], dv * acc[r][1],
                                                       dv * acc[r][2], dv * acc[r][3]);
                *(float4*)(C + base + 4) = make_float4(dv * acc[r][4], dv * acc[r][5],
                                                       dv * acc[r][6], dv * acc[r][7]);
            } else {  // MODE 3
                const float* ax = aux + (size_t)g * auxStride + (size_t)row * BN2 + tx * 8;
                float4 x0 = *(const float4*)ax;
                float4 x1 = *(const float4*)(ax + 4);
                const float4 bb0 = *(const float4*)(bias + tx * 8);
                const float4 bb1 = *(const float4*)(bias + tx * 8 + 4);
                float4 v0, v1;
                v0.x = fmaxf(0.5f * (acc[r][0] + x0.x) + bb0.x, 0.f);
                v0.y = fmaxf(0.5f * (acc[r][1] + x0.y) + bb0.y, 0.f);
                v0.z = fmaxf(0.5f * (acc[r][2] + x0.z) + bb0.z, 0.f);
                v0.w = fmaxf(0.5f * (acc[r][3] + x0.w) + bb0.w, 0.f);
                v1.x = fmaxf(0.5f * (acc[r][4] + x1.x) + bb1.x, 0.f);
                v1.y = fmaxf(0.5f * (acc[r][5] + x1.y) + bb1.y, 0.f);
                v1.z = fmaxf(0.5f * (acc[r][6] + x1.z) + bb1.z, 0.f);
                v1.w = fmaxf(0.5f * (acc[r][7] + x1.w) + bb1.w, 0.f);
                *(float4*)(C + base)     = v0;
                *(float4*)(C + base + 4) = v1;
            }
        }
    }
}

// ---------------- fused top-k + gather + attention dots ----------------------
template <int NTH, int KSEL>
__global__ void topk_gather_k(const float* __restrict__ sc,
                              const float* __restrict__ h, int Nsrc,
                              const float* __restrict__ atts,
                              const float* __restrict__ attd,
                              int* __restrict__ outIdx, float* __restrict__ xk,
                              float* __restrict__ xs, float* __restrict__ xd)
{
    __shared__ unsigned long long keys[NTH];
    __shared__ int sidx[KSEL];
    int g = blockIdx.x, t = threadIdx.x;
    float v = sc[g * NTH + t];
    unsigned u = __float_as_uint(v);
    u = (u & 0x80000000u) ? ~u : (u | 0x80000000u);
    keys[t] = (((unsigned long long)(~u)) << 32) | (unsigned)t;
    __syncthreads();
    for (int kk = 2; kk <= NTH; kk <<= 1) {
        for (int j = kk >> 1; j > 0; j >>= 1) {
            int ixj = t ^ j;
            if (ixj > t) {
                unsigned long long a = keys[t], b = keys[ixj];
                bool dir = ((t & kk) == 0);
                if ((a > b) == dir) { keys[t] = b; keys[ixj] = a; }
            }
            __syncthreads();
        }
    }
    if (t < KSEL) {
        int id = (int)(keys[t] & 0xffffffffu);
        sidx[t] = id;
        outIdx[g * KSEL + t] = id;
    }
    __syncthreads();

    int warp = t >> 5, lane = t & 31;
    const int nw = NTH / 32;
    float4 as4 = ((const float4*)atts)[lane];
    float4 ad4 = ((const float4*)attd)[lane];
    for (int i = warp; i < KSEL; i += nw) {
        int src = sidx[i];
        float4 vv = ((const float4*)(h + ((size_t)g * Nsrc + src) * FD))[lane];
        ((float4*)(xk + ((size_t)g * KSEL + i) * FD))[lane] = vv;
        float ps = vv.x * as4.x + vv.y * as4.y + vv.z * as4.z + vv.w * as4.w;
        float pd = vv.x * ad4.x + vv.y * ad4.y + vv.z * ad4.z + vv.w * ad4.w;
#pragma unroll
        for (int o = 16; o; o >>= 1) {
            ps += __shfl_xor_sync(0xffffffffu, ps, o);
            pd += __shfl_xor_sync(0xffffffffu, pd, o);
        }
        if (lane == 0) {
            xs[g * KSEL + i] = ps;
            xd[g * KSEL + i] = pd;
        }
    }
}

// -------- attention + softmax, phase A: warp-per-row, 8 rows/block -----------
__global__ __launch_bounds__(256)
void attn_bitmap8_k(const float* __restrict__ xs, const float* __restrict__ xd,
                    const int* __restrict__ idx, const unsigned* __restrict__ bits,
                    float* __restrict__ attn)
{
    __shared__ int   sidx[K1];
    __shared__ float sxd[K1];
    __shared__ unsigned sbw[8][N1 / 32];
    int g = blockIdx.y, t = threadIdx.x;
    int warp = t >> 5, lane = t & 31;
    int i = blockIdx.x * 8 + warp;

    sidx[t] = idx[g * K1 + t];
    sxd[t]  = xd[g * K1 + t];
    __syncthreads();

    int ii = sidx[i];
    if (lane < N1 / 32)
        sbw[warp][lane] = bits[((size_t)g * N1 + ii) * (N1 / 32) + lane];
    __syncwarp();

    float xsi = xs[g * K1 + i];
    int j0 = lane * 8;
    int4  i4a = ((const int4*)sidx)[lane * 2];
    int4  i4b = ((const int4*)sidx)[lane * 2 + 1];
    float4 xda = ((const float4*)sxd)[lane * 2];
    float4 xdb = ((const float4*)sxd)[lane * 2 + 1];
    int   jj[8] = {i4a.x, i4a.y, i4a.z, i4a.w, i4b.x, i4b.y, i4b.z, i4b.w};
    float xv[8] = {xda.x, xda.y, xda.z, xda.w, xdb.x, xdb.y, xdb.z, xdb.w};

    float e[8], mx = -3.402823466e+38f;
#pragma unroll
    for (int c = 0; c < 8; c++) {
        float v = xsi + xv[c];
        v = v > 0.f ? v : 0.2f * v;
        int q = jj[c];
        v += (float)((sbw[warp][q >> 5] >> (q & 31)) & 1u);
        e[c] = v;
        mx = fmaxf(mx, v);
    }
#pragma unroll
    for (int o = 16; o; o >>= 1) mx = fmaxf(mx, __shfl_xor_sync(0xffffffffu, mx, o));
    float p[8], s = 0.f;
#pragma unroll
    for (int c = 0; c < 8; c++) { p[c] = expf(e[c] - mx); s += p[c]; }
#pragma unroll
    for (int o = 16; o; o >>= 1) s += __shfl_xor_sync(0xffffffffu, s, o);
    float inv = 1.f / s;
    float* dst = attn + ((size_t)g * K1 + i) * K1 + j0;
    *(float4*)(dst)     = make_float4(p[0] * inv, p[1] * inv, p[2] * inv, p[3] * inv);
    *(float4*)(dst + 4) = make_float4(p[4] * inv, p[5] * inv, p[6] * inv, p[7] * inv);
}

// -------- attention + softmax, phase B: warp-per-row, 8 rows/block -----------
__global__ __launch_bounds__(256)
void attn_row8_k(const float* __restrict__ xs, const float* __restrict__ xd,
                 const int* __restrict__ idx, const float* __restrict__ adjsrc,
                 float* __restrict__ attn)
{
    __shared__ int   sidx[K2];
    __shared__ float sxd[K2];
    __shared__ float srow[8][K1];
    int g = blockIdx.y, t = threadIdx.x;
    int warp = t >> 5, lane = t & 31;
    int i = blockIdx.x * 8 + warp;

    if (t < K2) {
        sidx[t] = idx[g * K2 + t];
        sxd[t]  = xd[g * K2 + t];
    }
    __syncthreads();

    int ii = sidx[i];
    const float4* src4 = (const float4*)(adjsrc + ((size_t)g * K1 + ii) * K1);
    ((float4*)srow[warp])[lane]      = src4[lane];
    ((float4*)srow[warp])[lane + 32] = src4[lane + 32];
    __syncwarp();

    float xsi = xs[g * K2 + i];
    int j0 = lane * 4;
    int4   i4 = ((const int4*)sidx)[lane];
    float4 xv4 = ((const float4*)sxd)[lane];
    int   jj[4] = {i4.x, i4.y, i4.z, i4.w};
    float xv[4] = {xv4.x, xv4.y, xv4.z, xv4.w};

    float e[4], mx = -3.402823466e+38f;
#pragma unroll
    for (int c = 0; c < 4; c++) {
        float v = xsi + xv[c];
        v = v > 0.f ? v : 0.2f * v;
        v += srow[warp][jj[c]];
        e[c] = v;
        mx = fmaxf(mx, v);
    }
#pragma unroll
    for (int o = 16; o; o >>= 1) mx = fmaxf(mx, __shfl_xor_sync(0xffffffffu, mx, o));
    float p[4], s = 0.f;
#pragma unroll
    for (int c = 0; c < 4; c++) { p[c] = expf(e[c] - mx); s += p[c]; }
#pragma unroll
    for (int o = 16; o; o >>= 1) s += __shfl_xor_sync(0xffffffffu, s, o);
    float inv = 1.f / s;
    float* dst = attn + ((size_t)g * K2 + i) * K2 + j0;
    *(float4*)dst = make_float4(p[0] * inv, p[1] * inv, p[2] * inv, p[3] * inv);
}

// ------------------- fused readouts + MLP head (per graph) -------------------
__global__ void mlp_fused_k(const float* __restrict__ xk1,
                            const float* __restrict__ xk2,
                            const float* __restrict__ h3,
                            const float* __restrict__ Wl1, const float* __restrict__ bl1,
                            const float* __restrict__ Wl2, const float* __restrict__ bl2,
                            const float* __restrict__ Wl3, const float* __restrict__ bl3,
                            float* __restrict__ out)
{
    int g = blockIdx.x, t = threadIdx.x;   // 128 threads
    __shared__ float z[256], z1[128], z2[64], lg[NCLS];
    const float NEGINF = -3.402823466e+38f;

    float mx1 = NEGINF, sm1 = 0.f;
    for (int i = 0; i < K1; i++) {
        float v = xk1[((size_t)g * K1 + i) * FD + t];
        mx1 = fmaxf(mx1, v); sm1 += v;
    }
    float mx2 = NEGINF, sm2 = 0.f;
    for (int i = 0; i < K2; i++) {
        float v = xk2[((size_t)g * K2 + i) * FD + t];
        mx2 = fmaxf(mx2, v); sm2 += v;
    }
    float mx3 = NEGINF, sm3 = 0.f;
    for (int i = 0; i < K2; i++) {
        float v = h3[((size_t)g * K2 + i) * FD + t];
        mx3 = fmaxf(mx3, v); sm3 += v;
    }
    z[t]       = fmaxf(mx1, 0.f) + fmaxf(mx2, 0.f) + fmaxf(mx3, 0.f);
    z[128 + t] = fmaxf(sm1 / (float)K1, 0.f) + fmaxf(sm2 / (float)K2, 0.f)
               + fmaxf(sm3 / (float)K2, 0.f);
    __syncthreads();

    float a = bl1[t];
    for (int j = 0; j < 256; j++) a += z[j] * Wl1[j * 128 + t];
    z1[t] = fmaxf(a, 0.f);
    __syncthreads();
    if (t < 64) {
        float b = bl2[t];
        for (int j = 0; j < 128; j++) b += z1[j] * Wl2[j * 64 + t];
        z2[t] = fmaxf(b, 0.f);
    }
    __syncthreads();
    if (t < NCLS) {
        float c = bl3[t];
        for (int j = 0; j < 64; j++) c += z2[j] * Wl3[j * NCLS + t];
        lg[t] = c;
    }
    __syncthreads();
    if (t < NCLS) {
        float m = lg[0];
        for (int cc = 1; cc < NCLS; cc++) m = fmaxf(m, lg[cc]);
        float s = 0.f;
        for (int cc = 0; cc < NCLS; cc++) s += expf(lg[cc] - m);
        out[g * NCLS + t] = expf(lg[t] - m) / s;
    }
}

// ------------------------------ orchestration --------------------------------
extern "C" void kernel_launch(void* const* d_in, const int* in_sizes, int n_in,
                              void* d_out, int out_size)
{
    const float* x   = (const float*)d_in[0];
    const float* adj = (const float*)d_in[1];
    const float* W1  = (const float*)d_in[2];
    const float* b1  = (const float*)d_in[3];
    const float* W2  = (const float*)d_in[4];
    const float* b2  = (const float*)d_in[5];
    const float* W3  = (const float*)d_in[6];
    const float* b3  = (const float*)d_in[7];
    const float* a1s = (const float*)d_in[8];
    const float* a1d = (const float*)d_in[9];
    const float* a2s = (const float*)d_in[10];
    const float* a2d = (const float*)d_in[11];
    const float* Wl1 = (const float*)d_in[12];
    const float* bl1 = (const float*)d_in[13];
    const float* Wl2 = (const float*)d_in[14];
    const float* bl2 = (const float*)d_in[15];
    const float* Wl3 = (const float*)d_in[16];
    const float* bl3 = (const float*)d_in[17];
    float* out = (float*)d_out;

    float *p_dinv, *p_xw, *p_scr, *p_h1, *p_score, *p_xk1, *p_h2,
          *p_xk2, *p_h3, *p_attn1, *p_attn2, *p_xs, *p_xd;
    int *p_idx1, *p_idx2, *p_nnz, *p_cols;
    unsigned* p_bits;
    cudaGetSymbolAddress((void**)&p_dinv,  d_dinv);
    cudaGetSymbolAddress((void**)&p_nnz,   d_nnz);
    cudaGetSymbolAddress((void**)&p_cols,  d_cols);
    cudaGetSymbolAddress((void**)&p_bits,  d_bits);
    cudaGetSymbolAddress((void**)&p_xw,    d_xw);
    cudaGetSymbolAddress((void**)&p_scr,   d_scr);
    cudaGetSymbolAddress((void**)&p_h1,    d_h1);
    cudaGetSymbolAddress((void**)&p_score, d_score);
    cudaGetSymbolAddress((void**)&p_idx1,  d_idx1);
    cudaGetSymbolAddress((void**)&p_idx2,  d_idx2);
    cudaGetSymbolAddress((void**)&p_xk1,   d_xk1);
    cudaGetSymbolAddress((void**)&p_h2,    d_h2);
    cudaGetSymbolAddress((void**)&p_xk2,   d_xk2);
    cudaGetSymbolAddress((void**)&p_h3,    d_h3);
    cudaGetSymbolAddress((void**)&p_attn1, d_attn1);
    cudaGetSymbolAddress((void**)&p_attn2, d_attn2);
    cudaGetSymbolAddress((void**)&p_xs,    d_xs);
    cudaGetSymbolAddress((void**)&p_xd,    d_xd);

    // ---- Phase A (N = 512) ----
    build_k<<<(G * N1) / 8, 256>>>(adj, p_cols, p_nnz, p_dinv, p_bits);
    // y = dinv * (x @ W1)  -> d_scr  (xw never materialized)
    gemm_k<2><<<dim3(N1 / BM2, G), 256>>>(x, N1 * FD, FD, W1, 0,
                                          p_scr, N1 * FD, FD,
                                          nullptr, 0, p_dinv, N1, nullptr, nullptr);
    spmm_gcn1_k<<<(G * N1) / 8, 256>>>(p_scr, p_cols, p_nnz, p_dinv, b1, p_h1);
    spmm_score_k<<<(G * N1) / 8, 256>>>(p_h1, p_cols, p_nnz, p_score);
    topk_gather_k<N1, K1><<<G, N1>>>(p_score, p_h1, N1, a1s, a1d,
                                     p_idx1, p_xk1, p_xs, p_xd);
    attn_bitmap8_k<<<dim3(K1 / 8, G), 256>>>(p_xs, p_xd, p_idx1, p_bits, p_attn1);

    // ---- Phase B (N = 256) ----
    gemm_k<0><<<dim3(K1 / BM2, G), 256>>>(p_xk1, K1 * FD, FD, W2, 0,
                                          p_xw, K1 * FD, FD,
                                          nullptr, 0, nullptr, 0, nullptr, nullptr);
    gemm_k<3><<<dim3(K1 / BM2, G), 256>>>(p_attn1, K1 * K1, K1, p_xw, K1 * FD,
                                          p_h2, K1 * FD, K1,
                                          p_xw, K1 * FD, nullptr, 0, b2, nullptr);
    gemm_k<4><<<dim3(K1 / BM2, G), 256>>>(p_attn1, K1 * K1, K1, p_h2, K1 * FD,
                                          nullptr, K1, K1,
                                          p_h2, K1 * FD, nullptr, 0, nullptr, p_score);
    topk_gather_k<K1, K2><<<G, K1>>>(p_score, p_h2, K1, a2s, a2d,
                                     p_idx2, p_xk2, p_xs, p_xd);
    attn_row8_k<<<dim3(K2 / 8, G), 256>>>(p_xs, p_xd, p_idx2, p_attn1, p_attn2);

    // ---- Phase C (N = 128) ----
    gemm_k<0><<<dim3(K2 / BM2, G), 256>>>(p_xk2, K2 * FD, FD, W3, 0,
                                          p_xw, K2 * FD, FD,
                                          nullptr, 0, nullptr, 0, nullptr, nullptr);
    gemm_k<3><<<dim3(K2 / BM2, G), 256>>>(p_attn2, K2 * K2, K2, p_xw, K2 * FD,
                                          p_h3, K2 * FD, K2,
                                          p_xw, K2 * FD, nullptr, 0, b3, nullptr);

    // ---- Readouts + head (fused) ----
    mlp_fused_k<<<G, 128>>>(p_xk1, p_xk2, p_h3,
                            Wl1, bl1, Wl2, bl2, Wl3, bl3, out);
}